// round 2
// baseline (speedup 1.0000x reference)
#include <cuda_runtime.h>
#include <math_constants.h>

#define SEQ    8192
#define DMODEL 1024
#define DHEAD  128

typedef unsigned long long u64;

// ---------- packed f32x2 helpers (FFMA2 path: 2x fp32 FMA rate on sm_103a) ----------
__device__ __forceinline__ u64 pack2(float a, float b) {
    u64 r; asm("mov.b64 %0, {%1, %2};" : "=l"(r) : "f"(a), "f"(b)); return r;
}
__device__ __forceinline__ void unpack2(u64 v, float &a, float &b) {
    asm("mov.b64 {%0, %1}, %2;" : "=f"(a), "=f"(b) : "l"(v));
}
__device__ __forceinline__ void fma2(u64 &d, u64 a, u64 b) {
    asm("fma.rn.f32x2 %0, %1, %2, %0;" : "+l"(d) : "l"(a), "l"(b));
}
__device__ __forceinline__ void mul2(u64 &d, u64 a) {
    asm("mul.rn.f32x2 %0, %0, %1;" : "+l"(d) : "l"(a));
}

// ---------- scratch (device globals: no allocation allowed) ----------
__device__ float g_Q[SEQ * DHEAD];
__device__ float g_K[SEQ * DHEAD];
__device__ float g_V[SEQ * DHEAD];

// =====================================================================
// Kernel 1: QKV projection.  C[M,128] = X[M,1024] @ W[128,1024]^T
// BM=64, BN=128(all), BK=32, 256 threads, per-thread 4x8 via f32x2 k-pairs.
// =====================================================================
#define PBK  32
#define PSTR (PBK + 2)   // 34 (even -> 8B-aligned k-pair loads)

__global__ __launch_bounds__(256, 2)
void qkv_proj_kernel(const float* __restrict__ X,
                     const float* __restrict__ Wq,
                     const float* __restrict__ Wk,
                     const float* __restrict__ Wv)
{
    __shared__ __align__(16) float Xs[64][PSTR];
    __shared__ __align__(16) float Ws[128][PSTR];

    const int tid = threadIdx.x;
    const int tr  = tid >> 4;    // 0..15
    const int tc  = tid & 15;    // 0..15

    const int mblk = blockIdx.x * 64;
    const int w    = blockIdx.y;
    const float* __restrict__ W = (w == 0) ? Wq : (w == 1) ? Wk : Wv;
    float* __restrict__ C       = (w == 0) ? g_Q : (w == 1) ? g_K : g_V;
    const float scale = (w == 0) ? 0.08838834764831845f : 1.0f;  // 1/sqrt(128) folded into Q

    u64 acc[4][8];
    #pragma unroll
    for (int i = 0; i < 4; ++i)
        #pragma unroll
        for (int j = 0; j < 8; ++j) acc[i][j] = 0ull;   // (0.f,0.f)

    for (int k0 = 0; k0 < DMODEL; k0 += PBK) {
        // X tile 64x32 (512 float4)
        #pragma unroll
        for (int it = 0; it < 2; ++it) {
            int f = tid + it * 256;
            int row = f >> 3, c = (f & 7) * 4;
            const float4 v = *(const float4*)&X[(mblk + row) * DMODEL + k0 + c];
            float* dst = &Xs[row][c];
            *(float2*)dst       = make_float2(v.x, v.y);
            *(float2*)(dst + 2) = make_float2(v.z, v.w);
        }
        // W tile 128x32 (1024 float4)
        #pragma unroll
        for (int it = 0; it < 4; ++it) {
            int f = tid + it * 256;
            int row = f >> 3, c = (f & 7) * 4;
            const float4 v = *(const float4*)&W[row * DMODEL + k0 + c];
            float* dst = &Ws[row][c];
            *(float2*)dst       = make_float2(v.x, v.y);
            *(float2*)(dst + 2) = make_float2(v.z, v.w);
        }
        __syncthreads();

        #pragma unroll 8
        for (int kk = 0; kk < PBK; kk += 2) {
            u64 xv[4], wv[8];
            #pragma unroll
            for (int i = 0; i < 4; ++i)  xv[i]  = *(const u64*)&Xs[tr * 4 + i][kk];
            #pragma unroll
            for (int jj = 0; jj < 8; ++jj) wv[jj] = *(const u64*)&Ws[tc + 16 * jj][kk];
            #pragma unroll
            for (int i = 0; i < 4; ++i)
                #pragma unroll
                for (int jj = 0; jj < 8; ++jj)
                    fma2(acc[i][jj], xv[i], wv[jj]);
        }
        __syncthreads();
    }

    #pragma unroll
    for (int i = 0; i < 4; ++i) {
        int m = mblk + tr * 4 + i;
        #pragma unroll
        for (int jj = 0; jj < 8; ++jj) {
            float a, b; unpack2(acc[i][jj], a, b);
            C[m * DHEAD + tc + 16 * jj] = (a + b) * scale;
        }
    }
}

// =====================================================================
// Kernel 2: causal flash attention, fp32.
// 128 CTAs x 256 threads. Each CTA: paired 32-row q-blocks (b, 255-b),
// rows interleaved per-thread for load balance. BN=64 keys per tile.
// =====================================================================
#define QSTR 130
#define KSTR 130
#define VSTR 132
#define PPAD 65

struct SmemA {
    float Qs[64][QSTR];
    float Ks[64][KSTR];
    float Vs[64][VSTR];
    float Ps[64][PPAD];
};

template<int I0>
__device__ __forceinline__ void process_tile(SmemA& S, int j, const int grow[4],
                                             const int mloc[4],
                                             u64 O2[4][4], float mrow[4], float lrow[4],
                                             int tr, int tc)
{
    // ---- S = Q K^T (this thread: rows I0..3, cols tc+16*jj) ----
    u64 acc[4][4];
    #pragma unroll
    for (int i = I0; i < 4; ++i)
        #pragma unroll
        for (int jj = 0; jj < 4; ++jj) acc[i][jj] = 0ull;

    #pragma unroll 8
    for (int k = 0; k < DHEAD; k += 2) {
        u64 qv[4], kv[4];
        #pragma unroll
        for (int i = I0; i < 4; ++i)  qv[i]  = *(const u64*)&S.Qs[mloc[i]][k];
        #pragma unroll
        for (int jj = 0; jj < 4; ++jj) kv[jj] = *(const u64*)&S.Ks[tc + 16 * jj][k];
        #pragma unroll
        for (int i = I0; i < 4; ++i)
            #pragma unroll
            for (int jj = 0; jj < 4; ++jj)
                fma2(acc[i][jj], qv[i], kv[jj]);
    }

    // ---- online softmax update ----
    #pragma unroll
    for (int i = I0; i < 4; ++i) {
        float sv[4];
        float tmax = -CUDART_INF_F;
        #pragma unroll
        for (int jj = 0; jj < 4; ++jj) {
            float a, b; unpack2(acc[i][jj], a, b);
            float s = a + b;                        // Q pre-scaled by 1/sqrt(d)
            int col = j * 64 + tc + 16 * jj;
            s = (col <= grow[i]) ? s : -1e30f;      // causal mask
            sv[jj] = s;
            tmax = fmaxf(tmax, s);
        }
        #pragma unroll
        for (int mk = 8; mk >= 1; mk >>= 1)
            tmax = fmaxf(tmax, __shfl_xor_sync(0xffffffffu, tmax, mk));

        float mnew  = fmaxf(mrow[i], tmax);
        float alpha = __expf(mrow[i] - mnew);
        mrow[i] = mnew;

        float psum = 0.f;
        float pv[4];
        #pragma unroll
        for (int jj = 0; jj < 4; ++jj) {
            float p = __expf(sv[jj] - mnew);
            pv[jj] = p; psum += p;
        }
        #pragma unroll
        for (int mk = 8; mk >= 1; mk >>= 1)
            psum += __shfl_xor_sync(0xffffffffu, psum, mk);
        lrow[i] = lrow[i] * alpha + psum;

        u64 a2 = pack2(alpha, alpha);
        #pragma unroll
        for (int dj = 0; dj < 4; ++dj) mul2(O2[i][dj], a2);

        #pragma unroll
        for (int jj = 0; jj < 4; ++jj)
            S.Ps[mloc[i]][tc + 16 * jj] = pv[jj];
    }
    __syncthreads();

    // ---- O += P V  (this thread: rows I0..3, d = tc*8 .. tc*8+7) ----
    #pragma unroll 4
    for (int n = 0; n < 64; ++n) {
        const float4 va = *(const float4*)&S.Vs[n][tc * 8];
        const float4 vb = *(const float4*)&S.Vs[n][tc * 8 + 4];
        u64 v2[4];
        v2[0] = pack2(va.x, va.y); v2[1] = pack2(va.z, va.w);
        v2[2] = pack2(vb.x, vb.y); v2[3] = pack2(vb.z, vb.w);
        #pragma unroll
        for (int i = I0; i < 4; ++i) {
            float p = S.Ps[mloc[i]][n];
            u64 p2 = pack2(p, p);
            #pragma unroll
            for (int dj = 0; dj < 4; ++dj)
                fma2(O2[i][dj], p2, v2[dj]);
        }
    }
}

__global__ __launch_bounds__(256, 1)
void attn_kernel(float* __restrict__ Out)
{
    extern __shared__ __align__(16) char smem_raw[];
    SmemA& S = *reinterpret_cast<SmemA*>(smem_raw);

    const int tid = threadIdx.x;
    const int tr  = tid >> 4;   // 0..15
    const int tc  = tid & 15;   // 0..15
    const int b   = blockIdx.x; // 0..127

    const int q0 = b * 32;           // early q-block
    const int q1 = (255 - b) * 32;   // late q-block (paired for balance)

    const int mloc[4] = {2 * tr, 2 * tr + 1, 32 + 2 * tr, 33 + 2 * tr};
    int grow[4];
    grow[0] = q0 + 2 * tr; grow[1] = q0 + 2 * tr + 1;
    grow[2] = q1 + 2 * tr; grow[3] = q1 + 2 * tr + 1;

    // load Q (local rows 0..31 -> q0, 32..63 -> q1); already scaled by 1/sqrt(d)
    #pragma unroll
    for (int it = 0; it < 8; ++it) {
        int f = tid + it * 256;
        int lr = f >> 5, c = (f & 31) * 4;
        int gr = (lr < 32) ? (q0 + lr) : (q1 + lr - 32);
        const float4 v = *(const float4*)&g_Q[gr * DHEAD + c];
        float* dst = &S.Qs[lr][c];
        *(float2*)dst       = make_float2(v.x, v.y);
        *(float2*)(dst + 2) = make_float2(v.z, v.w);
    }

    u64 O2[4][4];
    #pragma unroll
    for (int i = 0; i < 4; ++i)
        #pragma unroll
        for (int j = 0; j < 4; ++j) O2[i][j] = 0ull;
    float mrow[4] = {-CUDART_INF_F, -CUDART_INF_F, -CUDART_INF_F, -CUDART_INF_F};
    float lrow[4] = {0.f, 0.f, 0.f, 0.f};

    const int t0 = (b + 2) >> 1;     // tiles with group0 still active
    const int t1 = (257 - b) >> 1;   // total tiles (group1 extent)

    for (int j = 0; j < t1; ++j) {
        // load K/V tile (64 keys x 128)
        #pragma unroll
        for (int it = 0; it < 8; ++it) {
            int f = tid + it * 256;
            int r = f >> 5, c = (f & 31) * 4;
            int g = (j * 64 + r) * DHEAD + c;
            const float4 kv = *(const float4*)&g_K[g];
            float* kd = &S.Ks[r][c];
            *(float2*)kd       = make_float2(kv.x, kv.y);
            *(float2*)(kd + 2) = make_float2(kv.z, kv.w);
            *(float4*)&S.Vs[r][c] = *(const float4*)&g_V[g];
        }
        __syncthreads();

        if (j < t0) process_tile<0>(S, j, grow, mloc, O2, mrow, lrow, tr, tc);
        else        process_tile<2>(S, j, grow, mloc, O2, mrow, lrow, tr, tc);
        __syncthreads();
    }

    // epilogue: normalize and store
    #pragma unroll
    for (int i = 0; i < 4; ++i) {
        float inv = 1.0f / lrow[i];
        float o[8];
        #pragma unroll
        for (int dj = 0; dj < 4; ++dj) {
            float a, c; unpack2(O2[i][dj], a, c);
            o[2 * dj] = a * inv; o[2 * dj + 1] = c * inv;
        }
        float4* dst = (float4*)&Out[grow[i] * DHEAD + tc * 8];
        dst[0] = make_float4(o[0], o[1], o[2], o[3]);
        dst[1] = make_float4(o[4], o[5], o[6], o[7]);
    }
}

// =====================================================================
extern "C" void kernel_launch(void* const* d_in, const int* in_sizes, int n_in,
                              void* d_out, int out_size)
{
    (void)in_sizes; (void)n_in; (void)out_size;
    const float* X  = (const float*)d_in[0];
    const float* Wq = (const float*)d_in[1];
    const float* Wk = (const float*)d_in[2];
    const float* Wv = (const float*)d_in[3];
    float* Out = (float*)d_out;

    dim3 pg(SEQ / 64, 3);
    qkv_proj_kernel<<<pg, 256>>>(X, Wq, Wk, Wv);

    const int smem = (int)sizeof(SmemA);
    cudaFuncSetAttribute(attn_kernel, cudaFuncAttributeMaxDynamicSharedMemorySize, smem);
    attn_kernel<<<128, 256, smem>>>(Out);
}

// round 4
// speedup vs baseline: 4.8575x; 4.8575x over previous
#include <cuda_runtime.h>
#include <cuda_bf16.h>
#include <cstdint>

typedef uint32_t u32;

#define SEQ 8192
#define DM  1024
#define DH  128

// ---------------- device scratch (no allocs allowed) ----------------
__device__ __align__(16) __nv_bfloat16 g_Qh[SEQ*DH], g_Ql[SEQ*DH];
__device__ __align__(16) __nv_bfloat16 g_Kh[SEQ*DH], g_Kl[SEQ*DH];
__device__ __align__(16) __nv_bfloat16 g_Vth[DH*SEQ], g_Vtl[DH*SEQ];  // V transposed [dim][seq]
__device__ float g_Op[4*SEQ*DH];
__device__ float g_mrow[4*SEQ], g_lrow[4*SEQ];

// ---------------- helpers ----------------
__device__ __forceinline__ u32 s2u(const void* p){
    u32 a; asm("{ .reg .u64 t; cvta.to.shared.u64 t, %1; cvt.u32.u64 %0, t; }" : "=r"(a) : "l"(p)); return a;
}
// pack {lo,hi} floats -> bf16x2 word (lo in low 16 bits)
__device__ __forceinline__ u32 pack_bf2(float lo, float hi){
    u32 r; asm("cvt.rn.satfinite.bf16x2.f32 %0, %1, %2;" : "=r"(r) : "f"(hi), "f"(lo)); return r;
}
__device__ __forceinline__ float bflo(u32 v){ return __uint_as_float(v << 16); }
__device__ __forceinline__ float bfhi(u32 v){ return __uint_as_float(v & 0xffff0000u); }
__device__ __forceinline__ void split2(float a, float b, u32 &h, u32 &l){
    h = pack_bf2(a, b);
    l = pack_bf2(a - bflo(h), b - bfhi(h));
}
__device__ __forceinline__ void ldsm4(u32 a, u32 &r0, u32 &r1, u32 &r2, u32 &r3){
    asm volatile("ldmatrix.sync.aligned.m8n8.x4.shared.b16 {%0,%1,%2,%3}, [%4];"
        : "=r"(r0), "=r"(r1), "=r"(r2), "=r"(r3) : "r"(a));
}
__device__ __forceinline__ void mma16816(float* d, u32 a0, u32 a1, u32 a2, u32 a3, u32 b0, u32 b1){
    asm volatile("mma.sync.aligned.m16n8k16.row.col.f32.bf16.bf16.f32 "
        "{%0,%1,%2,%3},{%4,%5,%6,%7},{%8,%9},{%0,%1,%2,%3};"
        : "+f"(d[0]), "+f"(d[1]), "+f"(d[2]), "+f"(d[3])
        : "r"(a0), "r"(a1), "r"(a2), "r"(a3), "r"(b0), "r"(b1));
}

// =====================================================================
// Kernel 1: QKV projection. grid(64, 3), 256 thr (8 warps, 4m x 2n).
// C[128,128] tile = X[128,1024] @ W[128,1024]^T, split-bf16 3-term.
// Outputs split-bf16 Q (scaled), K row-major; V transposed [dim][seq].
// =====================================================================
#define PSB 144   // proj smem row stride bytes (72 bf16 elems)

__global__ void __launch_bounds__(256,1) proj_kernel(const float* __restrict__ X,
        const float* __restrict__ Wq, const float* __restrict__ Wk, const float* __restrict__ Wv)
{
    extern __shared__ __align__(16) char sm[];
    char* Xh = sm;           char* Xl = sm + 18432;
    char* Wh = sm + 36864;   char* Wl = sm + 55296;
    const u32 sXh = s2u(Xh), sXl = s2u(Xl), sWh = s2u(Wh), sWl = s2u(Wl);

    const int tid  = threadIdx.x, lane = tid & 31, wid = tid >> 5;
    const int wm   = wid >> 1, wn = wid & 1;
    const int m0   = blockIdx.x * 128, mat = blockIdx.y;
    const float* __restrict__ W = (mat==0) ? Wq : (mat==1) ? Wk : Wv;
    const float scale = (mat==0) ? 0.08838834764831845f : 1.0f;

    const int aRow = lane & 15, aKB = (lane >> 4) << 3;
    const int bRow = (lane & 7) + ((lane >> 4) & 1) * 8, bKB = ((lane >> 3) & 1) << 3;

    float acc[2][8][4];
    #pragma unroll
    for (int i = 0; i < 2; ++i)
        #pragma unroll
        for (int j = 0; j < 8; ++j)
            #pragma unroll
            for (int c = 0; c < 4; ++c) acc[i][j][c] = 0.f;

    for (int kc = 0; kc < 16; ++kc) {
        __syncthreads();
        #pragma unroll
        for (int it = 0; it < 16; ++it) {
            int idx = tid + it * 256;
            int r = idx >> 5, c2 = idx & 31;
            float2 xv = *(const float2*)&X[(size_t)(m0 + r)*DM + kc*64 + c2*2];
            u32 h, l; split2(xv.x, xv.y, h, l);
            *(u32*)(Xh + r*PSB + c2*4) = h;
            *(u32*)(Xl + r*PSB + c2*4) = l;
            float2 wv = *(const float2*)&W[(size_t)r*DM + kc*64 + c2*2];
            split2(wv.x, wv.y, h, l);
            *(u32*)(Wh + r*PSB + c2*4) = h;
            *(u32*)(Wl + r*PSB + c2*4) = l;
        }
        __syncthreads();

        #pragma unroll
        for (int ks = 0; ks < 4; ++ks) {
            u32 ah[2][4], al[2][4];
            #pragma unroll
            for (int mt = 0; mt < 2; ++mt) {
                u32 qa = (u32)((wm*32 + mt*16 + aRow)*PSB + (ks*16 + aKB)*2);
                ldsm4(sXh + qa, ah[mt][0], ah[mt][1], ah[mt][2], ah[mt][3]);
                ldsm4(sXl + qa, al[mt][0], al[mt][1], al[mt][2], al[mt][3]);
            }
            #pragma unroll
            for (int nbp = 0; nbp < 4; ++nbp) {
                u32 bh[4], bl[4];
                u32 ba = (u32)((wn*64 + nbp*16 + bRow)*PSB + (ks*16 + bKB)*2);
                ldsm4(sWh + ba, bh[0], bh[1], bh[2], bh[3]);
                ldsm4(sWl + ba, bl[0], bl[1], bl[2], bl[3]);
                #pragma unroll
                for (int mt = 0; mt < 2; ++mt) {
                    mma16816(acc[mt][nbp*2],   ah[mt][0],ah[mt][1],ah[mt][2],ah[mt][3], bh[0], bh[1]);
                    mma16816(acc[mt][nbp*2],   ah[mt][0],ah[mt][1],ah[mt][2],ah[mt][3], bl[0], bl[1]);
                    mma16816(acc[mt][nbp*2],   al[mt][0],al[mt][1],al[mt][2],al[mt][3], bh[0], bh[1]);
                    mma16816(acc[mt][nbp*2+1], ah[mt][0],ah[mt][1],ah[mt][2],ah[mt][3], bh[2], bh[3]);
                    mma16816(acc[mt][nbp*2+1], ah[mt][0],ah[mt][1],ah[mt][2],ah[mt][3], bl[2], bl[3]);
                    mma16816(acc[mt][nbp*2+1], al[mt][0],al[mt][1],al[mt][2],al[mt][3], bh[2], bh[3]);
                }
            }
        }
    }

    // epilogue
    #pragma unroll
    for (int mt = 0; mt < 2; ++mt) {
        const int r0 = m0 + wm*32 + mt*16 + (lane >> 2);
        const int r1 = r0 + 8;
        #pragma unroll
        for (int nt = 0; nt < 8; ++nt) {
            const int col = wn*64 + nt*8 + (lane & 3)*2;
            float c0 = acc[mt][nt][0]*scale, c1 = acc[mt][nt][1]*scale;
            float c2 = acc[mt][nt][2]*scale, c3 = acc[mt][nt][3]*scale;
            if (mat < 2) {
                __nv_bfloat16* GH = (mat==0) ? g_Qh : g_Kh;
                __nv_bfloat16* GL = (mat==0) ? g_Ql : g_Kl;
                u32 h, l;
                split2(c0, c1, h, l);
                *(u32*)&GH[(size_t)r0*DH + col] = h;  *(u32*)&GL[(size_t)r0*DH + col] = l;
                split2(c2, c3, h, l);
                *(u32*)&GH[(size_t)r1*DH + col] = h;  *(u32*)&GL[(size_t)r1*DH + col] = l;
            } else {
                float v[4] = {c0, c1, c2, c3};
                #pragma unroll
                for (int e = 0; e < 4; ++e) {
                    int d  = col + (e & 1);
                    int sq = (e < 2) ? r0 : r1;
                    __nv_bfloat16 h = __float2bfloat16_rn(v[e]);
                    g_Vth[(size_t)d*SEQ + sq] = h;
                    g_Vtl[(size_t)d*SEQ + sq] = __float2bfloat16_rn(v[e] - __bfloat162float(h));
                }
            }
        }
    }
}

// =====================================================================
// Kernel 2: causal flash attention (FA2-style, split-bf16 3-term).
// 128 CTAs x 256 thr. CTA (qq,pp): quarter qq of q-tiles pp and 63-pp.
// Warp owns 16 q-rows; softmax quad-local; P converts in-register.
// =====================================================================
#define ASB 272   // attn smem row stride bytes (136 bf16 elems)

__global__ void __launch_bounds__(256,1) attn_kernel()
{
    extern __shared__ __align__(16) char sm[];
    char* Qh = sm;            char* Ql = sm + 34816;
    char* Kh = sm + 69632;    char* Kl = sm + 104448;
    char* Vh = sm + 139264;   char* Vl = sm + 174080;
    const u32 sQh = s2u(Qh), sQl = s2u(Ql), sKh = s2u(Kh), sKl = s2u(Kl);
    const u32 sVh = s2u(Vh), sVl = s2u(Vl);

    const int tid = threadIdx.x, lane = tid & 31, w = tid >> 5;
    const int qq = blockIdx.x >> 5;   // kv quarter 0..3
    const int pp = blockIdx.x & 31;   // pair id 0..31

    const int aRow = lane & 15, aKB = (lane >> 4) << 3;
    const int bRow = (lane & 7) + ((lane >> 4) & 1) * 8, bKB = ((lane >> 3) & 1) << 3;
    const int rl0 = w*16 + (lane >> 2);   // local q-row of c0/c1
    const int rl1 = rl0 + 8;              // local q-row of c2/c3

    #pragma unroll 1
    for (int u = 0; u < 2; ++u) {
        const int i  = u ? (63 - pp) : pp;
        const int T  = i + 1;
        const int Tq = (T + 3) >> 2;
        const int j0 = qq * Tq;
        const int j1 = (j0 + Tq < T) ? (j0 + Tq) : T;
        const int brow = qq*SEQ + i*128;

        if (j0 >= j1) {
            if (tid < 128) { g_mrow[brow + tid] = -1e30f; g_lrow[brow + tid] = 0.f; }
            continue;
        }

        __syncthreads();
        // load Q tile (split bf16)
        #pragma unroll
        for (int it = 0; it < 8; ++it) {
            int idx = tid + it*256;
            int r = idx >> 4, c = idx & 15;
            *(uint4*)(Qh + r*ASB + c*16) = *(const uint4*)&g_Qh[(size_t)(i*128 + r)*DH + c*8];
            *(uint4*)(Ql + r*ASB + c*16) = *(const uint4*)&g_Ql[(size_t)(i*128 + r)*DH + c*8];
        }

        float o[16][4];
        #pragma unroll
        for (int nt = 0; nt < 16; ++nt)
            #pragma unroll
            for (int c = 0; c < 4; ++c) o[nt][c] = 0.f;
        float m0r = -1e30f, m1r = -1e30f, l0 = 0.f, l1 = 0.f;

        #pragma unroll 1
        for (int j = j0; j < j1; ++j) {
            __syncthreads();   // prev PV reads done; safe to overwrite K/V
            #pragma unroll
            for (int it = 0; it < 8; ++it) {
                int idx = tid + it*256;
                int r = idx >> 4, c = idx & 15;
                *(uint4*)(Kh + r*ASB + c*16) = *(const uint4*)&g_Kh [(size_t)(j*128 + r)*DH + c*8];
                *(uint4*)(Kl + r*ASB + c*16) = *(const uint4*)&g_Kl [(size_t)(j*128 + r)*DH + c*8];
                *(uint4*)(Vh + r*ASB + c*16) = *(const uint4*)&g_Vth[(size_t)r*SEQ + j*128 + c*8];
                *(uint4*)(Vl + r*ASB + c*16) = *(const uint4*)&g_Vtl[(size_t)r*SEQ + j*128 + c*8];
            }
            __syncthreads();

            // ---- S = Q K^T ----
            float s[16][4];
            #pragma unroll
            for (int nt = 0; nt < 16; ++nt)
                #pragma unroll
                for (int c = 0; c < 4; ++c) s[nt][c] = 0.f;

            #pragma unroll
            for (int ks = 0; ks < 8; ++ks) {
                u32 qh[4], ql[4];
                u32 qa = (u32)((w*16 + aRow)*ASB + (ks*16 + aKB)*2);
                ldsm4(sQh + qa, qh[0], qh[1], qh[2], qh[3]);
                ldsm4(sQl + qa, ql[0], ql[1], ql[2], ql[3]);
                #pragma unroll
                for (int nbp = 0; nbp < 8; ++nbp) {
                    u32 kh[4], kl[4];
                    u32 ba = (u32)((nbp*16 + bRow)*ASB + (ks*16 + bKB)*2);
                    ldsm4(sKh + ba, kh[0], kh[1], kh[2], kh[3]);
                    ldsm4(sKl + ba, kl[0], kl[1], kl[2], kl[3]);
                    mma16816(s[nbp*2],   qh[0],qh[1],qh[2],qh[3], kh[0], kh[1]);
                    mma16816(s[nbp*2],   qh[0],qh[1],qh[2],qh[3], kl[0], kl[1]);
                    mma16816(s[nbp*2],   ql[0],ql[1],ql[2],ql[3], kh[0], kh[1]);
                    mma16816(s[nbp*2+1], qh[0],qh[1],qh[2],qh[3], kh[2], kh[3]);
                    mma16816(s[nbp*2+1], qh[0],qh[1],qh[2],qh[3], kl[2], kl[3]);
                    mma16816(s[nbp*2+1], ql[0],ql[1],ql[2],ql[3], kh[2], kh[3]);
                }
            }

            // ---- causal mask (diagonal tile only) ----
            if (j == i) {
                #pragma unroll
                for (int nt = 0; nt < 16; ++nt) {
                    int c0 = nt*8 + (lane & 3)*2;
                    if (c0     > rl0) s[nt][0] = -1e30f;
                    if (c0 + 1 > rl0) s[nt][1] = -1e30f;
                    if (c0     > rl1) s[nt][2] = -1e30f;
                    if (c0 + 1 > rl1) s[nt][3] = -1e30f;
                }
            }

            // ---- online softmax (rows are quad-local) ----
            float mx0 = -1e30f, mx1 = -1e30f;
            #pragma unroll
            for (int nt = 0; nt < 16; ++nt) {
                mx0 = fmaxf(mx0, fmaxf(s[nt][0], s[nt][1]));
                mx1 = fmaxf(mx1, fmaxf(s[nt][2], s[nt][3]));
            }
            mx0 = fmaxf(mx0, __shfl_xor_sync(0xffffffffu, mx0, 1));
            mx0 = fmaxf(mx0, __shfl_xor_sync(0xffffffffu, mx0, 2));
            mx1 = fmaxf(mx1, __shfl_xor_sync(0xffffffffu, mx1, 1));
            mx1 = fmaxf(mx1, __shfl_xor_sync(0xffffffffu, mx1, 2));

            float mn0 = fmaxf(m0r, mx0), mn1 = fmaxf(m1r, mx1);
            float al0 = __expf(m0r - mn0), al1 = __expf(m1r - mn1);

            u32 ph2[32], pl2[32];
            float sum0 = 0.f, sum1 = 0.f;
            #pragma unroll
            for (int nt = 0; nt < 16; ++nt) {
                float p0 = __expf(s[nt][0] - mn0);
                float p1 = __expf(s[nt][1] - mn0);
                float p2 = __expf(s[nt][2] - mn1);
                float p3 = __expf(s[nt][3] - mn1);
                sum0 += p0 + p1;  sum1 += p2 + p3;
                split2(p0, p1, ph2[nt*2],   pl2[nt*2]);
                split2(p2, p3, ph2[nt*2+1], pl2[nt*2+1]);
            }
            sum0 += __shfl_xor_sync(0xffffffffu, sum0, 1);
            sum0 += __shfl_xor_sync(0xffffffffu, sum0, 2);
            sum1 += __shfl_xor_sync(0xffffffffu, sum1, 1);
            sum1 += __shfl_xor_sync(0xffffffffu, sum1, 2);

            l0 = l0*al0 + sum0;  l1 = l1*al1 + sum1;
            m0r = mn0;  m1r = mn1;

            #pragma unroll
            for (int nt = 0; nt < 16; ++nt) {
                o[nt][0] *= al0;  o[nt][1] *= al0;
                o[nt][2] *= al1;  o[nt][3] *= al1;
            }

            // ---- O += P V (A-frags come straight from ph2/pl2) ----
            #pragma unroll
            for (int t = 0; t < 8; ++t) {
                #pragma unroll
                for (int nbp = 0; nbp < 8; ++nbp) {
                    u32 vh[4], vl[4];
                    u32 ba = (u32)((nbp*16 + bRow)*ASB + (t*16 + bKB)*2);
                    ldsm4(sVh + ba, vh[0], vh[1], vh[2], vh[3]);
                    ldsm4(sVl + ba, vl[0], vl[1], vl[2], vl[3]);
                    mma16816(o[nbp*2],   ph2[4*t],ph2[4*t+1],ph2[4*t+2],ph2[4*t+3], vh[0], vh[1]);
                    mma16816(o[nbp*2],   ph2[4*t],ph2[4*t+1],ph2[4*t+2],ph2[4*t+3], vl[0], vl[1]);
                    mma16816(o[nbp*2],   pl2[4*t],pl2[4*t+1],pl2[4*t+2],pl2[4*t+3], vh[0], vh[1]);
                    mma16816(o[nbp*2+1], ph2[4*t],ph2[4*t+1],ph2[4*t+2],ph2[4*t+3], vh[2], vh[3]);
                    mma16816(o[nbp*2+1], ph2[4*t],ph2[4*t+1],ph2[4*t+2],ph2[4*t+3], vl[2], vl[3]);
                    mma16816(o[nbp*2+1], pl2[4*t],pl2[4*t+1],pl2[4*t+2],pl2[4*t+3], vh[2], vh[3]);
                }
            }
        }

        // ---- store partials ----
        const int gr0 = brow + rl0, gr1 = brow + rl1;
        #pragma unroll
        for (int nt = 0; nt < 16; ++nt) {
            const int col = nt*8 + (lane & 3)*2;
            *(float2*)&g_Op[(size_t)gr0*DH + col] = make_float2(o[nt][0], o[nt][1]);
            *(float2*)&g_Op[(size_t)gr1*DH + col] = make_float2(o[nt][2], o[nt][3]);
        }
        if ((lane & 3) == 0) {
            g_mrow[gr0] = m0r;  g_lrow[gr0] = l0;
            g_mrow[gr1] = m1r;  g_lrow[gr1] = l1;
        }
    }
}

// =====================================================================
// Kernel 3: merge 4 KV-quarter partials per row (LSE combine).
// =====================================================================
__global__ void merge_kernel(float* __restrict__ Out)
{
    const int row = blockIdx.x;
    const int d = threadIdx.x;
    float mv[4], lv[4];
    float mmax = -1e30f;
    #pragma unroll
    for (int q = 0; q < 4; ++q) {
        mv[q] = g_mrow[q*SEQ + row];
        lv[q] = g_lrow[q*SEQ + row];
        if (lv[q] > 0.f) mmax = fmaxf(mmax, mv[q]);
    }
    float acc = 0.f, ws = 0.f;
    #pragma unroll
    for (int q = 0; q < 4; ++q) {
        if (lv[q] > 0.f) {
            float wgt = __expf(mv[q] - mmax);
            acc += wgt * g_Op[((size_t)q*SEQ + row)*DH + d];
            ws  += wgt * lv[q];
        }
    }
    Out[(size_t)row*DH + d] = acc / ws;
}

// =====================================================================
extern "C" void kernel_launch(void* const* d_in, const int* in_sizes, int n_in,
                              void* d_out, int out_size)
{
    (void)in_sizes; (void)n_in; (void)out_size;
    const float* X  = (const float*)d_in[0];
    const float* Wq = (const float*)d_in[1];
    const float* Wk = (const float*)d_in[2];
    const float* Wv = (const float*)d_in[3];

    const int PSM = 73728;
    const int ASM = 208896;
    cudaFuncSetAttribute(proj_kernel, cudaFuncAttributeMaxDynamicSharedMemorySize, PSM);
    cudaFuncSetAttribute(attn_kernel, cudaFuncAttributeMaxDynamicSharedMemorySize, ASM);

    proj_kernel<<<dim3(64, 3), 256, PSM>>>(X, Wq, Wk, Wv);
    attn_kernel<<<128, 256, ASM>>>();
    merge_kernel<<<SEQ, 128>>>((float*)d_out);
}

// round 5
// speedup vs baseline: 4.8921x; 1.0071x over previous
#include <cuda_runtime.h>
#include <cuda_bf16.h>
#include <cstdint>

typedef uint32_t u32;

#define SEQ 8192
#define DM  1024
#define DH  128

#define NEGINF __int_as_float(0xff800000u)

// ---------------- device scratch (no allocs allowed) ----------------
__device__ __align__(16) __nv_bfloat16 g_Xh[SEQ*DM],  g_Xl[SEQ*DM];
__device__ __align__(16) __nv_bfloat16 g_Wh[3*DH*DM], g_Wl[3*DH*DM];
__device__ __align__(16) __nv_bfloat16 g_Qh[SEQ*DH],  g_Ql[SEQ*DH];
__device__ __align__(16) __nv_bfloat16 g_Kh[SEQ*DH],  g_Kl[SEQ*DH];
__device__ __align__(16) __nv_bfloat16 g_Vth[DH*SEQ], g_Vtl[DH*SEQ];  // V transposed [dim][seq]
__device__ float g_Op[4*SEQ*DH];
__device__ float g_mrow[4*SEQ], g_lrow[4*SEQ];

// ---------------- helpers ----------------
__device__ __forceinline__ u32 s2u(const void* p){
    u32 a; asm("{ .reg .u64 t; cvta.to.shared.u64 t, %1; cvt.u32.u64 %0, t; }" : "=r"(a) : "l"(p)); return a;
}
__device__ __forceinline__ u32 pack_bf2(float lo, float hi){
    u32 r; asm("cvt.rn.satfinite.bf16x2.f32 %0, %1, %2;" : "=r"(r) : "f"(hi), "f"(lo)); return r;
}
__device__ __forceinline__ float bflo(u32 v){ return __uint_as_float(v << 16); }
__device__ __forceinline__ float bfhi(u32 v){ return __uint_as_float(v & 0xffff0000u); }
__device__ __forceinline__ void split2(float a, float b, u32 &h, u32 &l){
    h = pack_bf2(a, b);
    l = pack_bf2(a - bflo(h), b - bfhi(h));
}
__device__ __forceinline__ void ldsm4(u32 a, u32 &r0, u32 &r1, u32 &r2, u32 &r3){
    asm volatile("ldmatrix.sync.aligned.m8n8.x4.shared.b16 {%0,%1,%2,%3}, [%4];"
        : "=r"(r0), "=r"(r1), "=r"(r2), "=r"(r3) : "r"(a));
}
__device__ __forceinline__ void mma16816(float* d, u32 a0, u32 a1, u32 a2, u32 a3, u32 b0, u32 b1){
    asm volatile("mma.sync.aligned.m16n8k16.row.col.f32.bf16.bf16.f32 "
        "{%0,%1,%2,%3},{%4,%5,%6,%7},{%8,%9},{%0,%1,%2,%3};"
        : "+f"(d[0]), "+f"(d[1]), "+f"(d[2]), "+f"(d[3])
        : "r"(a0), "r"(a1), "r"(a2), "r"(a3), "r"(b0), "r"(b1));
}
__device__ __forceinline__ void cpa16(u32 dst, const void* src){
    asm volatile("cp.async.cg.shared.global [%0], [%1], 16;" :: "r"(dst), "l"(src));
}
#define CPCOMMIT() asm volatile("cp.async.commit_group;" ::: "memory")
#define CPWAIT0()  asm volatile("cp.async.wait_group 0;" ::: "memory")

// =====================================================================
// Kernel 0: fp32 -> split bf16 (hi + residual lo)
// =====================================================================
__global__ void split_kernel(const float4* __restrict__ src,
                             uint2* __restrict__ dh, uint2* __restrict__ dl, int n4)
{
    int i = blockIdx.x * blockDim.x + threadIdx.x;
    if (i >= n4) return;
    float4 v = src[i];
    u32 h0, l0, h1, l1;
    split2(v.x, v.y, h0, l0);
    split2(v.z, v.w, h1, l1);
    dh[i] = make_uint2(h0, h1);
    dl[i] = make_uint2(l0, l1);
}

// =====================================================================
// Kernel 1: QKV projection, split-bf16 3-term, cp.async 2-stage.
// grid(128, 3): M-tile 64. 256 thr = 8 warps (2m x 4n).
// smem/stage: Xh,Xl 64x144B; Wh,Wl 128x144B  (55296B; 2 stages)
// =====================================================================
#define PSB   144
#define PXH   0
#define PXL   9216
#define PWH   18432
#define PWL   36864
#define PSSZ  55296

__global__ void __launch_bounds__(256,1) proj_kernel()
{
    extern __shared__ __align__(16) char sm[];
    const u32 sb = s2u(sm);

    const int tid = threadIdx.x, lane = tid & 31, wid = tid >> 5;
    const int wm = wid >> 2, wn = wid & 3;       // 2m x 4n
    const int m0 = blockIdx.x * 64, mat = blockIdx.y;
    const __nv_bfloat16* __restrict__ Wbh = g_Wh + (size_t)mat*DH*DM;
    const __nv_bfloat16* __restrict__ Wbl = g_Wl + (size_t)mat*DH*DM;
    const float scale = (mat==0) ? 0.08838834764831845f : 1.0f;

    const int aRow = lane & 15, aKB = (lane >> 4) << 3;
    const int bRow = (lane & 7) + ((lane >> 4) & 1) * 8, bKB = ((lane >> 3) & 1) << 3;

    auto issue = [&](int kc, int st){
        const u32 base = sb + st*PSSZ;
        // X: 64 rows x 8 x16B, hi+lo
        #pragma unroll
        for (int it = 0; it < 2; ++it) {
            int idx = tid + it*256;            // 0..511
            int r = idx >> 3, c = idx & 7;
            cpa16(base + PXH + r*PSB + c*16, &g_Xh[(size_t)(m0 + r)*DM + kc*64 + c*8]);
            cpa16(base + PXL + r*PSB + c*16, &g_Xl[(size_t)(m0 + r)*DM + kc*64 + c*8]);
        }
        // W: 128 rows x 8 x16B, hi+lo
        #pragma unroll
        for (int it = 0; it < 4; ++it) {
            int idx = tid + it*256;            // 0..1023
            int r = idx >> 3, c = idx & 7;
            cpa16(base + PWH + r*PSB + c*16, &Wbh[(size_t)r*DM + kc*64 + c*8]);
            cpa16(base + PWL + r*PSB + c*16, &Wbl[(size_t)r*DM + kc*64 + c*8]);
        }
        CPCOMMIT();
    };

    float acc[2][4][4];
    #pragma unroll
    for (int i = 0; i < 2; ++i)
        #pragma unroll
        for (int j = 0; j < 4; ++j)
            #pragma unroll
            for (int c = 0; c < 4; ++c) acc[i][j][c] = 0.f;

    issue(0, 0);
    for (int kc = 0; kc < 16; ++kc) {
        const int st = kc & 1;
        const u32 base = sb + st*PSSZ;
        CPWAIT0();
        __syncthreads();
        if (kc + 1 < 16) issue(kc + 1, st ^ 1);

        #pragma unroll
        for (int ks = 0; ks < 4; ++ks) {
            u32 ah[2][4], al[2][4];
            #pragma unroll
            for (int mt = 0; mt < 2; ++mt) {
                u32 qa = base + PXH + (u32)((wm*32 + mt*16 + aRow)*PSB + (ks*16 + aKB)*2);
                ldsm4(qa,           ah[mt][0], ah[mt][1], ah[mt][2], ah[mt][3]);
                ldsm4(qa + (PXL-PXH), al[mt][0], al[mt][1], al[mt][2], al[mt][3]);
            }
            #pragma unroll
            for (int nb = 0; nb < 2; ++nb) {
                u32 bh[4], bl[4];
                u32 ba = base + PWH + (u32)((wn*32 + nb*16 + bRow)*PSB + (ks*16 + bKB)*2);
                ldsm4(ba,            bh[0], bh[1], bh[2], bh[3]);
                ldsm4(ba + (PWL-PWH), bl[0], bl[1], bl[2], bl[3]);
                #pragma unroll
                for (int mt = 0; mt < 2; ++mt) {
                    mma16816(acc[mt][nb*2],   ah[mt][0],ah[mt][1],ah[mt][2],ah[mt][3], bh[0], bh[1]);
                    mma16816(acc[mt][nb*2],   ah[mt][0],ah[mt][1],ah[mt][2],ah[mt][3], bl[0], bl[1]);
                    mma16816(acc[mt][nb*2],   al[mt][0],al[mt][1],al[mt][2],al[mt][3], bh[0], bh[1]);
                    mma16816(acc[mt][nb*2+1], ah[mt][0],ah[mt][1],ah[mt][2],ah[mt][3], bh[2], bh[3]);
                    mma16816(acc[mt][nb*2+1], ah[mt][0],ah[mt][1],ah[mt][2],ah[mt][3], bl[2], bl[3]);
                    mma16816(acc[mt][nb*2+1], al[mt][0],al[mt][1],al[mt][2],al[mt][3], bh[2], bh[3]);
                }
            }
        }
        __syncthreads();
    }

    // epilogue: split outputs; Q scaled; V transposed
    #pragma unroll
    for (int mt = 0; mt < 2; ++mt) {
        const int r0 = m0 + wm*32 + mt*16 + (lane >> 2);
        const int r1 = r0 + 8;
        #pragma unroll
        for (int nt = 0; nt < 4; ++nt) {
            const int col = wn*32 + nt*8 + (lane & 3)*2;
            float c0 = acc[mt][nt][0]*scale, c1 = acc[mt][nt][1]*scale;
            float c2 = acc[mt][nt][2]*scale, c3 = acc[mt][nt][3]*scale;
            if (mat < 2) {
                __nv_bfloat16* GH = (mat==0) ? g_Qh : g_Kh;
                __nv_bfloat16* GL = (mat==0) ? g_Ql : g_Kl;
                u32 h, l;
                split2(c0, c1, h, l);
                *(u32*)&GH[(size_t)r0*DH + col] = h;  *(u32*)&GL[(size_t)r0*DH + col] = l;
                split2(c2, c3, h, l);
                *(u32*)&GH[(size_t)r1*DH + col] = h;  *(u32*)&GL[(size_t)r1*DH + col] = l;
            } else {
                float v[4] = {c0, c1, c2, c3};
                #pragma unroll
                for (int e = 0; e < 4; ++e) {
                    int d  = col + (e & 1);
                    int sq = (e < 2) ? r0 : r1;
                    __nv_bfloat16 h = __float2bfloat16_rn(v[e]);
                    g_Vth[(size_t)d*SEQ + sq] = h;
                    g_Vtl[(size_t)d*SEQ + sq] = __float2bfloat16_rn(v[e] - __bfloat162float(h));
                }
            }
        }
    }
}

// =====================================================================
// Kernel 2: causal flash attention, split-bf16 3-term, cp.async 2-stage.
// 128 CTAs x 256 thr. CTA (qq,pp): KV-quarter qq of q-tiles pp & 63-pp.
// KV subtile = 64 keys. smem: Q(hi,lo) + 2 stages of {Kh,Kl,Vh,Vl}.
// =====================================================================
#define ASB   272                 // Q/K row stride (128 kcols)
#define VSB   144                 // V row stride (64 key cols)
#define AQH   0
#define AQL   34816
#define ASTG  69632               // stage base
#define SKH   0
#define SKL   17408
#define SVH   34816
#define SVL   53248
#define ASSZ  71680               // stage size
// total = 69632 + 2*71680 = 212992

__global__ void __launch_bounds__(256,1) attn_kernel()
{
    extern __shared__ __align__(16) char sm[];
    const u32 sb = s2u(sm);

    const int tid = threadIdx.x, lane = tid & 31, w = tid >> 5;
    const int qq = blockIdx.x >> 5;   // kv quarter 0..3
    const int pp = blockIdx.x & 31;   // pair id 0..31

    const int aRow = lane & 15, aKB = (lane >> 4) << 3;
    const int bRow = (lane & 7) + ((lane >> 4) & 1) * 8, bKB = ((lane >> 3) & 1) << 3;
    const int rl0 = w*16 + (lane >> 2);
    const int rl1 = rl0 + 8;

    #pragma unroll 1
    for (int u = 0; u < 2; ++u) {
        const int i  = u ? (63 - pp) : pp;
        const int T2 = 2*(i + 1);              // 64-key subtiles
        const int Tq = (T2 + 3) >> 2;
        const int j0 = qq * Tq;
        const int j1 = (j0 + Tq < T2) ? (j0 + Tq) : T2;
        const int brow = qq*SEQ + i*128;

        if (j0 >= j1) {
            if (tid < 128) { g_mrow[brow + tid] = NEGINF; g_lrow[brow + tid] = 0.f; }
            continue;
        }

        auto issueKV = [&](int j, int st){
            const u32 base = sb + ASTG + st*ASSZ;
            #pragma unroll
            for (int it = 0; it < 4; ++it) {     // K: 64 rows x 16 x16B
                int idx = tid + it*256;
                int r = idx >> 4, c = idx & 15;
                cpa16(base + SKH + r*ASB + c*16, &g_Kh[(size_t)(j*64 + r)*DH + c*8]);
                cpa16(base + SKL + r*ASB + c*16, &g_Kl[(size_t)(j*64 + r)*DH + c*8]);
            }
            #pragma unroll
            for (int it = 0; it < 4; ++it) {     // V: 128 dim-rows x 8 x16B
                int idx = tid + it*256;
                int r = idx >> 3, c = idx & 7;
                cpa16(base + SVH + r*VSB + c*16, &g_Vth[(size_t)r*SEQ + j*64 + c*8]);
                cpa16(base + SVL + r*VSB + c*16, &g_Vtl[(size_t)r*SEQ + j*64 + c*8]);
            }
            CPCOMMIT();
        };

        // prologue: Q + first KV
        #pragma unroll
        for (int it = 0; it < 8; ++it) {
            int idx = tid + it*256;
            int r = idx >> 4, c = idx & 15;
            cpa16(sb + AQH + r*ASB + c*16, &g_Qh[(size_t)(i*128 + r)*DH + c*8]);
            cpa16(sb + AQL + r*ASB + c*16, &g_Ql[(size_t)(i*128 + r)*DH + c*8]);
        }
        CPCOMMIT();
        issueKV(j0, 0);

        float o[16][4];
        #pragma unroll
        for (int nt = 0; nt < 16; ++nt)
            #pragma unroll
            for (int c = 0; c < 4; ++c) o[nt][c] = 0.f;
        float m0r = NEGINF, m1r = NEGINF, l0 = 0.f, l1 = 0.f;

        #pragma unroll 1
        for (int j = j0; j < j1; ++j) {
            const int st = (j - j0) & 1;
            const u32 base = sb + ASTG + st*ASSZ;
            CPWAIT0();
            __syncthreads();
            if (j + 1 < j1) issueKV(j + 1, st ^ 1);

            // ---- S = Q K^T (this subtile: 64 keys) ----
            float s[8][4];
            #pragma unroll
            for (int nt = 0; nt < 8; ++nt)
                #pragma unroll
                for (int c = 0; c < 4; ++c) s[nt][c] = 0.f;

            #pragma unroll
            for (int ks = 0; ks < 8; ++ks) {
                u32 qh[4], ql[4];
                u32 qa = sb + AQH + (u32)((w*16 + aRow)*ASB + (ks*16 + aKB)*2);
                ldsm4(qa,             qh[0], qh[1], qh[2], qh[3]);
                ldsm4(qa + (AQL-AQH), ql[0], ql[1], ql[2], ql[3]);
                #pragma unroll
                for (int nbp = 0; nbp < 4; ++nbp) {
                    u32 kh[4], kl[4];
                    u32 ba = base + SKH + (u32)((nbp*16 + bRow)*ASB + (ks*16 + bKB)*2);
                    ldsm4(ba,             kh[0], kh[1], kh[2], kh[3]);
                    ldsm4(ba + (SKL-SKH), kl[0], kl[1], kl[2], kl[3]);
                    mma16816(s[nbp*2],   qh[0],qh[1],qh[2],qh[3], kh[0], kh[1]);
                    mma16816(s[nbp*2],   qh[0],qh[1],qh[2],qh[3], kl[0], kl[1]);
                    mma16816(s[nbp*2],   ql[0],ql[1],ql[2],ql[3], kh[0], kh[1]);
                    mma16816(s[nbp*2+1], qh[0],qh[1],qh[2],qh[3], kh[2], kh[3]);
                    mma16816(s[nbp*2+1], qh[0],qh[1],qh[2],qh[3], kl[2], kl[3]);
                    mma16816(s[nbp*2+1], ql[0],ql[1],ql[2],ql[3], kh[2], kh[3]);
                }
            }

            // ---- causal mask ----
            if (j*64 + 63 > i*128) {
                const int gr0 = i*128 + rl0, gr1 = i*128 + rl1;
                #pragma unroll
                for (int nt = 0; nt < 8; ++nt) {
                    int gc = j*64 + nt*8 + (lane & 3)*2;
                    if (gc     > gr0) s[nt][0] = NEGINF;
                    if (gc + 1 > gr0) s[nt][1] = NEGINF;
                    if (gc     > gr1) s[nt][2] = NEGINF;
                    if (gc + 1 > gr1) s[nt][3] = NEGINF;
                }
            }

            // ---- online softmax (quad-local rows) ----
            float mx0 = NEGINF, mx1 = NEGINF;
            #pragma unroll
            for (int nt = 0; nt < 8; ++nt) {
                mx0 = fmaxf(mx0, fmaxf(s[nt][0], s[nt][1]));
                mx1 = fmaxf(mx1, fmaxf(s[nt][2], s[nt][3]));
            }
            mx0 = fmaxf(mx0, __shfl_xor_sync(0xffffffffu, mx0, 1));
            mx0 = fmaxf(mx0, __shfl_xor_sync(0xffffffffu, mx0, 2));
            mx1 = fmaxf(mx1, __shfl_xor_sync(0xffffffffu, mx1, 1));
            mx1 = fmaxf(mx1, __shfl_xor_sync(0xffffffffu, mx1, 2));

            float mn0 = fmaxf(m0r, mx0), mn1 = fmaxf(m1r, mx1);
            float mue0 = (mn0 == NEGINF) ? 0.f : mn0;   // guard fully-masked rows
            float mue1 = (mn1 == NEGINF) ? 0.f : mn1;
            float al0 = __expf(m0r - mue0), al1 = __expf(m1r - mue1);

            u32 ph2[16], pl2[16];
            float sum0 = 0.f, sum1 = 0.f;
            #pragma unroll
            for (int nt = 0; nt < 8; ++nt) {
                float p0 = __expf(s[nt][0] - mue0);
                float p1 = __expf(s[nt][1] - mue0);
                float p2 = __expf(s[nt][2] - mue1);
                float p3 = __expf(s[nt][3] - mue1);
                sum0 += p0 + p1;  sum1 += p2 + p3;
                split2(p0, p1, ph2[nt*2],   pl2[nt*2]);
                split2(p2, p3, ph2[nt*2+1], pl2[nt*2+1]);
            }
            sum0 += __shfl_xor_sync(0xffffffffu, sum0, 1);
            sum0 += __shfl_xor_sync(0xffffffffu, sum0, 2);
            sum1 += __shfl_xor_sync(0xffffffffu, sum1, 1);
            sum1 += __shfl_xor_sync(0xffffffffu, sum1, 2);

            l0 = l0*al0 + sum0;  l1 = l1*al1 + sum1;
            m0r = mn0;  m1r = mn1;

            #pragma unroll
            for (int nt = 0; nt < 16; ++nt) {
                o[nt][0] *= al0;  o[nt][1] *= al0;
                o[nt][2] *= al1;  o[nt][3] *= al1;
            }

            // ---- O += P V ----
            #pragma unroll
            for (int t = 0; t < 4; ++t) {
                #pragma unroll
                for (int nbp = 0; nbp < 8; ++nbp) {
                    u32 vh[4], vl[4];
                    u32 ba = base + SVH + (u32)((nbp*16 + bRow)*VSB + (t*16 + bKB)*2);
                    ldsm4(ba,             vh[0], vh[1], vh[2], vh[3]);
                    ldsm4(ba + (SVL-SVH), vl[0], vl[1], vl[2], vl[3]);
                    mma16816(o[nbp*2],   ph2[4*t],ph2[4*t+1],ph2[4*t+2],ph2[4*t+3], vh[0], vh[1]);
                    mma16816(o[nbp*2],   ph2[4*t],ph2[4*t+1],ph2[4*t+2],ph2[4*t+3], vl[0], vl[1]);
                    mma16816(o[nbp*2],   pl2[4*t],pl2[4*t+1],pl2[4*t+2],pl2[4*t+3], vh[0], vh[1]);
                    mma16816(o[nbp*2+1], ph2[4*t],ph2[4*t+1],ph2[4*t+2],ph2[4*t+3], vh[2], vh[3]);
                    mma16816(o[nbp*2+1], ph2[4*t],ph2[4*t+1],ph2[4*t+2],ph2[4*t+3], vl[2], vl[3]);
                    mma16816(o[nbp*2+1], pl2[4*t],pl2[4*t+1],pl2[4*t+2],pl2[4*t+3], vh[2], vh[3]);
                }
            }
            __syncthreads();
        }

        // ---- store partials ----
        const int gr0 = brow + rl0, gr1 = brow + rl1;
        #pragma unroll
        for (int nt = 0; nt < 16; ++nt) {
            const int col = nt*8 + (lane & 3)*2;
            *(float2*)&g_Op[(size_t)gr0*DH + col] = make_float2(o[nt][0], o[nt][1]);
            *(float2*)&g_Op[(size_t)gr1*DH + col] = make_float2(o[nt][2], o[nt][3]);
        }
        if ((lane & 3) == 0) {
            g_mrow[gr0] = m0r;  g_lrow[gr0] = l0;
            g_mrow[gr1] = m1r;  g_lrow[gr1] = l1;
        }
    }
}

// =====================================================================
// Kernel 3: merge 4 KV-quarter partials per row (LSE combine).
// =====================================================================
__global__ void merge_kernel(float* __restrict__ Out)
{
    const int row = blockIdx.x;
    const int d = threadIdx.x;
    float mv[4], lv[4];
    float mmax = NEGINF;
    #pragma unroll
    for (int q = 0; q < 4; ++q) {
        mv[q] = g_mrow[q*SEQ + row];
        lv[q] = g_lrow[q*SEQ + row];
        if (lv[q] > 0.f) mmax = fmaxf(mmax, mv[q]);
    }
    float acc = 0.f, ws = 0.f;
    #pragma unroll
    for (int q = 0; q < 4; ++q) {
        if (lv[q] > 0.f) {
            float wgt = __expf(mv[q] - mmax);
            acc += wgt * g_Op[((size_t)q*SEQ + row)*DH + d];
            ws  += wgt * lv[q];
        }
    }
    Out[(size_t)row*DH + d] = acc / ws;
}

// =====================================================================
extern "C" void kernel_launch(void* const* d_in, const int* in_sizes, int n_in,
                              void* d_out, int out_size)
{
    (void)in_sizes; (void)n_in; (void)out_size;
    const float* X  = (const float*)d_in[0];
    const float* Wq = (const float*)d_in[1];
    const float* Wk = (const float*)d_in[2];
    const float* Wv = (const float*)d_in[3];

    __nv_bfloat16 *xh, *xl, *wh, *wl;
    cudaGetSymbolAddress((void**)&xh, g_Xh);
    cudaGetSymbolAddress((void**)&xl, g_Xl);
    cudaGetSymbolAddress((void**)&wh, g_Wh);
    cudaGetSymbolAddress((void**)&wl, g_Wl);

    const int nX4 = SEQ*DM/4, nW4 = DH*DM/4;
    split_kernel<<<nX4/256, 256>>>((const float4*)X,  (uint2*)xh, (uint2*)xl, nX4);
    split_kernel<<<nW4/256, 256>>>((const float4*)Wq, (uint2*)(wh),           (uint2*)(wl),           nW4);
    split_kernel<<<nW4/256, 256>>>((const float4*)Wk, (uint2*)(wh + DH*DM),   (uint2*)(wl + DH*DM),   nW4);
    split_kernel<<<nW4/256, 256>>>((const float4*)Wv, (uint2*)(wh + 2*DH*DM), (uint2*)(wl + 2*DH*DM), nW4);

    const int PSM = 2*PSSZ;                 // 110592
    const int ASM = ASTG + 2*ASSZ;          // 212992
    cudaFuncSetAttribute(proj_kernel, cudaFuncAttributeMaxDynamicSharedMemorySize, PSM);
    cudaFuncSetAttribute(attn_kernel, cudaFuncAttributeMaxDynamicSharedMemorySize, ASM);

    proj_kernel<<<dim3(128, 3), 256, PSM>>>();
    attn_kernel<<<128, 256, ASM>>>();
    merge_kernel<<<SEQ, 128>>>((float*)d_out);
}

// round 6
// speedup vs baseline: 5.0036x; 1.0228x over previous
#include <cuda_runtime.h>
#include <cuda_bf16.h>
#include <cstdint>

typedef uint32_t u32;

#define SEQ 8192
#define DM  1024
#define DH  128

#define NEGINF __int_as_float(0xff800000u)

// ---------------- device scratch (no allocs allowed) ----------------
__device__ __align__(16) __nv_bfloat16 g_Xh[SEQ*DM],  g_Xl[SEQ*DM];
__device__ __align__(16) __nv_bfloat16 g_Wh[3*DH*DM], g_Wl[3*DH*DM];
__device__ __align__(16) __nv_bfloat16 g_Qh[SEQ*DH],  g_Ql[SEQ*DH];
__device__ __align__(16) __nv_bfloat16 g_Kh[SEQ*DH],  g_Kl[SEQ*DH];
__device__ __align__(16) __nv_bfloat16 g_Vth[DH*SEQ], g_Vtl[DH*SEQ];  // V transposed [dim][seq]
__device__ float g_Op[4*SEQ*DH];
__device__ float g_mrow[4*SEQ], g_lrow[4*SEQ];

// ---------------- helpers ----------------
__device__ __forceinline__ u32 s2u(const void* p){
    u32 a; asm("{ .reg .u64 t; cvta.to.shared.u64 t, %1; cvt.u32.u64 %0, t; }" : "=r"(a) : "l"(p)); return a;
}
__device__ __forceinline__ u32 pack_bf2(float lo, float hi){
    u32 r; asm("cvt.rn.satfinite.bf16x2.f32 %0, %1, %2;" : "=r"(r) : "f"(hi), "f"(lo)); return r;
}
__device__ __forceinline__ float bflo(u32 v){ return __uint_as_float(v << 16); }
__device__ __forceinline__ float bfhi(u32 v){ return __uint_as_float(v & 0xffff0000u); }
__device__ __forceinline__ void split2(float a, float b, u32 &h, u32 &l){
    h = pack_bf2(a, b);
    l = pack_bf2(a - bflo(h), b - bfhi(h));
}
__device__ __forceinline__ void ldsm4(u32 a, u32 &r0, u32 &r1, u32 &r2, u32 &r3){
    asm volatile("ldmatrix.sync.aligned.m8n8.x4.shared.b16 {%0,%1,%2,%3}, [%4];"
        : "=r"(r0), "=r"(r1), "=r"(r2), "=r"(r3) : "r"(a));
}
__device__ __forceinline__ void mma16816(float* d, u32 a0, u32 a1, u32 a2, u32 a3, u32 b0, u32 b1){
    asm volatile("mma.sync.aligned.m16n8k16.row.col.f32.bf16.bf16.f32 "
        "{%0,%1,%2,%3},{%4,%5,%6,%7},{%8,%9},{%0,%1,%2,%3};"
        : "+f"(d[0]), "+f"(d[1]), "+f"(d[2]), "+f"(d[3])
        : "r"(a0), "r"(a1), "r"(a2), "r"(a3), "r"(b0), "r"(b1));
}
__device__ __forceinline__ void cpa16(u32 dst, const void* src){
    asm volatile("cp.async.cg.shared.global [%0], [%1], 16;" :: "r"(dst), "l"(src));
}
#define CPCOMMIT() asm volatile("cp.async.commit_group;" ::: "memory")
#define CPWAIT0()  asm volatile("cp.async.wait_group 0;" ::: "memory")

// =====================================================================
// Kernel 0: fp32 -> split bf16 for X and the 3 W matrices (one launch)
// =====================================================================
__global__ void split_all_kernel(const float4* __restrict__ X,
                                 const float4* __restrict__ Wq,
                                 const float4* __restrict__ Wk,
                                 const float4* __restrict__ Wv)
{
    const int nX4 = SEQ*DM/4, nW4 = DH*DM/4;
    int i = blockIdx.x * blockDim.x + threadIdx.x;
    const float4* src; uint2 *dh, *dl; int off;
    if (i < nX4) {
        src = X; off = i;
        dh = (uint2*)g_Xh; dl = (uint2*)g_Xl;
    } else {
        int k = i - nX4;
        if (k >= 3*nW4) return;
        int mat = k / nW4; off = k - mat*nW4;
        src = (mat==0) ? Wq : (mat==1) ? Wk : Wv;
        dh = (uint2*)(g_Wh + (size_t)mat*DH*DM);
        dl = (uint2*)(g_Wl + (size_t)mat*DH*DM);
    }
    float4 v = src[off];
    u32 h0, l0, h1, l1;
    split2(v.x, v.y, h0, l0);
    split2(v.z, v.w, h1, l1);
    dh[off] = make_uint2(h0, h1);
    dl[off] = make_uint2(l0, l1);
}

// =====================================================================
// Kernel 1: QKV projection, split-bf16 3-term, cp.async 2-stage.
// grid(128, 3): M-tile 64. 256 thr = 8 warps (2m x 4n).
// =====================================================================
#define PSB   144
#define PXH   0
#define PXL   9216
#define PWH   18432
#define PWL   36864
#define PSSZ  55296

__global__ void __launch_bounds__(256,1) proj_kernel()
{
    extern __shared__ __align__(16) char sm[];
    const u32 sb = s2u(sm);

    const int tid = threadIdx.x, lane = tid & 31, wid = tid >> 5;
    const int wm = wid >> 2, wn = wid & 3;       // 2m x 4n
    const int m0 = blockIdx.x * 64, mat = blockIdx.y;
    const __nv_bfloat16* __restrict__ Wbh = g_Wh + (size_t)mat*DH*DM;
    const __nv_bfloat16* __restrict__ Wbl = g_Wl + (size_t)mat*DH*DM;
    const float scale = (mat==0) ? 0.08838834764831845f : 1.0f;

    const int aRow = lane & 15, aKB = (lane >> 4) << 3;
    const int bRow = (lane & 7) + ((lane >> 4) & 1) * 8, bKB = ((lane >> 3) & 1) << 3;

    auto issue = [&](int kc, int st){
        const u32 base = sb + st*PSSZ;
        #pragma unroll
        for (int it = 0; it < 2; ++it) {
            int idx = tid + it*256;
            int r = idx >> 3, c = idx & 7;
            cpa16(base + PXH + r*PSB + c*16, &g_Xh[(size_t)(m0 + r)*DM + kc*64 + c*8]);
            cpa16(base + PXL + r*PSB + c*16, &g_Xl[(size_t)(m0 + r)*DM + kc*64 + c*8]);
        }
        #pragma unroll
        for (int it = 0; it < 4; ++it) {
            int idx = tid + it*256;
            int r = idx >> 3, c = idx & 7;
            cpa16(base + PWH + r*PSB + c*16, &Wbh[(size_t)r*DM + kc*64 + c*8]);
            cpa16(base + PWL + r*PSB + c*16, &Wbl[(size_t)r*DM + kc*64 + c*8]);
        }
        CPCOMMIT();
    };

    float acc[2][4][4];
    #pragma unroll
    for (int i = 0; i < 2; ++i)
        #pragma unroll
        for (int j = 0; j < 4; ++j)
            #pragma unroll
            for (int c = 0; c < 4; ++c) acc[i][j][c] = 0.f;

    issue(0, 0);
    for (int kc = 0; kc < 16; ++kc) {
        const int st = kc & 1;
        const u32 base = sb + st*PSSZ;
        CPWAIT0();
        __syncthreads();
        if (kc + 1 < 16) issue(kc + 1, st ^ 1);

        #pragma unroll
        for (int ks = 0; ks < 4; ++ks) {
            u32 ah[2][4], al[2][4];
            #pragma unroll
            for (int mt = 0; mt < 2; ++mt) {
                u32 qa = base + PXH + (u32)((wm*32 + mt*16 + aRow)*PSB + (ks*16 + aKB)*2);
                ldsm4(qa,             ah[mt][0], ah[mt][1], ah[mt][2], ah[mt][3]);
                ldsm4(qa + (PXL-PXH), al[mt][0], al[mt][1], al[mt][2], al[mt][3]);
            }
            #pragma unroll
            for (int nb = 0; nb < 2; ++nb) {
                u32 bh[4], bl[4];
                u32 ba = base + PWH + (u32)((wn*32 + nb*16 + bRow)*PSB + (ks*16 + bKB)*2);
                ldsm4(ba,             bh[0], bh[1], bh[2], bh[3]);
                ldsm4(ba + (PWL-PWH), bl[0], bl[1], bl[2], bl[3]);
                #pragma unroll
                for (int mt = 0; mt < 2; ++mt) {
                    mma16816(acc[mt][nb*2],   ah[mt][0],ah[mt][1],ah[mt][2],ah[mt][3], bh[0], bh[1]);
                    mma16816(acc[mt][nb*2],   ah[mt][0],ah[mt][1],ah[mt][2],ah[mt][3], bl[0], bl[1]);
                    mma16816(acc[mt][nb*2],   al[mt][0],al[mt][1],al[mt][2],al[mt][3], bh[0], bh[1]);
                    mma16816(acc[mt][nb*2+1], ah[mt][0],ah[mt][1],ah[mt][2],ah[mt][3], bh[2], bh[3]);
                    mma16816(acc[mt][nb*2+1], ah[mt][0],ah[mt][1],ah[mt][2],ah[mt][3], bl[2], bl[3]);
                    mma16816(acc[mt][nb*2+1], al[mt][0],al[mt][1],al[mt][2],al[mt][3], bh[2], bh[3]);
                }
            }
        }
        __syncthreads();
    }

    #pragma unroll
    for (int mt = 0; mt < 2; ++mt) {
        const int r0 = m0 + wm*32 + mt*16 + (lane >> 2);
        const int r1 = r0 + 8;
        #pragma unroll
        for (int nt = 0; nt < 4; ++nt) {
            const int col = wn*32 + nt*8 + (lane & 3)*2;
            float c0 = acc[mt][nt][0]*scale, c1 = acc[mt][nt][1]*scale;
            float c2 = acc[mt][nt][2]*scale, c3 = acc[mt][nt][3]*scale;
            if (mat < 2) {
                __nv_bfloat16* GH = (mat==0) ? g_Qh : g_Kh;
                __nv_bfloat16* GL = (mat==0) ? g_Ql : g_Kl;
                u32 h, l;
                split2(c0, c1, h, l);
                *(u32*)&GH[(size_t)r0*DH + col] = h;  *(u32*)&GL[(size_t)r0*DH + col] = l;
                split2(c2, c3, h, l);
                *(u32*)&GH[(size_t)r1*DH + col] = h;  *(u32*)&GL[(size_t)r1*DH + col] = l;
            } else {
                float v[4] = {c0, c1, c2, c3};
                #pragma unroll
                for (int e = 0; e < 4; ++e) {
                    int d  = col + (e & 1);
                    int sq = (e < 2) ? r0 : r1;
                    __nv_bfloat16 h = __float2bfloat16_rn(v[e]);
                    g_Vth[(size_t)d*SEQ + sq] = h;
                    g_Vtl[(size_t)d*SEQ + sq] = __float2bfloat16_rn(v[e] - __bfloat162float(h));
                }
            }
        }
    }
}

// =====================================================================
// Kernel 2: causal flash attention, split-bf16 3-term, software-
// pipelined: S(j+1) MMA interleaves with softmax(j); K/V prefetch
// issued at iteration top (full-iteration overlap, 2 stages each).
// 128 CTAs x 256 thr. CTA (qq,pp): KV-quarter qq of q-tiles pp & 63-pp.
// =====================================================================
#define ASB   272                 // Q/K row stride bytes (128 kcols)
#define VSB   144                 // V row stride bytes (64 key cols)
#define AQH   0
#define AQL   34816
#define KST   69632               // K stages base
#define KSTG  34816               // per K stage (hi 0 / lo +17408)
#define KKL   17408
#define VST   139264              // V stages base
#define VSTG  36864               // per V stage (hi 0 / lo +18432)
#define VVL   18432
// total = 139264 + 2*36864 = 212992

__global__ void __launch_bounds__(256,1) attn_kernel()
{
    extern __shared__ __align__(16) char sm[];
    const u32 sb = s2u(sm);

    const int tid = threadIdx.x, lane = tid & 31, w = tid >> 5;
    const int qq = blockIdx.x >> 5;   // kv quarter 0..3
    const int pp = blockIdx.x & 31;   // pair id 0..31

    const int aRow = lane & 15, aKB = (lane >> 4) << 3;
    const int bRow = (lane & 7) + ((lane >> 4) & 1) * 8, bKB = ((lane >> 3) & 1) << 3;
    const int rl0 = w*16 + (lane >> 2);
    const int rl1 = rl0 + 8;

    auto issueK = [&](int j){
        const u32 base = sb + KST + (u32)(j & 1)*KSTG;
        #pragma unroll
        for (int it = 0; it < 4; ++it) {
            int idx = tid + it*256;
            int r = idx >> 4, c = idx & 15;
            cpa16(base       + r*ASB + c*16, &g_Kh[(size_t)(j*64 + r)*DH + c*8]);
            cpa16(base + KKL + r*ASB + c*16, &g_Kl[(size_t)(j*64 + r)*DH + c*8]);
        }
    };
    auto issueV = [&](int j){
        const u32 base = sb + VST + (u32)(j & 1)*VSTG;
        #pragma unroll
        for (int it = 0; it < 4; ++it) {
            int idx = tid + it*256;
            int r = idx >> 3, c = idx & 7;
            cpa16(base       + r*VSB + c*16, &g_Vth[(size_t)r*SEQ + j*64 + c*8]);
            cpa16(base + VVL + r*VSB + c*16, &g_Vtl[(size_t)r*SEQ + j*64 + c*8]);
        }
    };

    // S = Q K^T for 64-key subtile j -> s
    auto S_mma = [&](int j, float (&s)[8][4]){
        const u32 kb = sb + KST + (u32)(j & 1)*KSTG;
        #pragma unroll
        for (int nt = 0; nt < 8; ++nt)
            #pragma unroll
            for (int c = 0; c < 4; ++c) s[nt][c] = 0.f;
        #pragma unroll
        for (int ks = 0; ks < 8; ++ks) {
            u32 qh[4], ql[4];
            u32 qa = sb + AQH + (u32)((w*16 + aRow)*ASB + (ks*16 + aKB)*2);
            ldsm4(qa,             qh[0], qh[1], qh[2], qh[3]);
            ldsm4(qa + (AQL-AQH), ql[0], ql[1], ql[2], ql[3]);
            #pragma unroll
            for (int nbp = 0; nbp < 4; ++nbp) {
                u32 kh[4], kl[4];
                u32 ba = kb + (u32)((nbp*16 + bRow)*ASB + (ks*16 + bKB)*2);
                ldsm4(ba,       kh[0], kh[1], kh[2], kh[3]);
                ldsm4(ba + KKL, kl[0], kl[1], kl[2], kl[3]);
                mma16816(s[nbp*2],   qh[0],qh[1],qh[2],qh[3], kh[0], kh[1]);
                mma16816(s[nbp*2],   qh[0],qh[1],qh[2],qh[3], kl[0], kl[1]);
                mma16816(s[nbp*2],   ql[0],ql[1],ql[2],ql[3], kh[0], kh[1]);
                mma16816(s[nbp*2+1], qh[0],qh[1],qh[2],qh[3], kh[2], kh[3]);
                mma16816(s[nbp*2+1], qh[0],qh[1],qh[2],qh[3], kl[2], kl[3]);
                mma16816(s[nbp*2+1], ql[0],ql[1],ql[2],ql[3], kh[2], kh[3]);
            }
        }
    };

    #pragma unroll 1
    for (int u = 0; u < 2; ++u) {
        const int i  = u ? (63 - pp) : pp;
        const int T2 = 2*(i + 1);              // 64-key subtiles
        const int Tq = (T2 + 3) >> 2;
        const int j0 = qq * Tq;
        const int j1 = (j0 + Tq < T2) ? (j0 + Tq) : T2;
        const int brow = qq*SEQ + i*128;

        if (j0 >= j1) {
            if (tid < 128) { g_mrow[brow + tid] = NEGINF; g_lrow[brow + tid] = 0.f; }
            continue;
        }

        __syncthreads();   // protect Q smem from prior unit's readers
        // prologue: Q + K(j0) + V(j0) + K(j0+1)
        #pragma unroll
        for (int it = 0; it < 8; ++it) {
            int idx = tid + it*256;
            int r = idx >> 4, c = idx & 15;
            cpa16(sb + AQH + r*ASB + c*16, &g_Qh[(size_t)(i*128 + r)*DH + c*8]);
            cpa16(sb + AQL + r*ASB + c*16, &g_Ql[(size_t)(i*128 + r)*DH + c*8]);
        }
        issueK(j0);
        issueV(j0);
        if (j0 + 1 < j1) issueK(j0 + 1);
        CPCOMMIT();
        CPWAIT0();
        __syncthreads();

        float o[16][4];
        #pragma unroll
        for (int nt = 0; nt < 16; ++nt)
            #pragma unroll
            for (int c = 0; c < 4; ++c) o[nt][c] = 0.f;
        float m0r = NEGINF, m1r = NEGINF, l0 = 0.f, l1 = 0.f;

        float sA[8][4], sB[8][4];
        u32 ph2[16], pl2[16];

        S_mma(j0, sA);

        // one pipeline step: softmax+PV on s(j), with S(j+1) MMA interleaved
        auto step = [&](int j, float (&sc)[8][4], float (&sn)[8][4]){
            CPWAIT0();            // g_{j-1}: K(j+1), V(j) landed (no-op at j0)
            __syncthreads();
            const bool hn = (j + 1 < j1);
            if (hn) {             // prefetch with full-iteration overlap
                issueV(j + 1);
                if (j + 2 < j1) issueK(j + 2);
                CPCOMMIT();
            }
            if (hn) S_mma(j + 1, sn);   // independent of softmax(j) below

            // ---- causal mask ----
            if (j*64 + 63 > i*128) {
                const int gr0 = i*128 + rl0, gr1 = i*128 + rl1;
                #pragma unroll
                for (int nt = 0; nt < 8; ++nt) {
                    int gc = j*64 + nt*8 + (lane & 3)*2;
                    if (gc     > gr0) sc[nt][0] = NEGINF;
                    if (gc + 1 > gr0) sc[nt][1] = NEGINF;
                    if (gc     > gr1) sc[nt][2] = NEGINF;
                    if (gc + 1 > gr1) sc[nt][3] = NEGINF;
                }
            }

            // ---- online softmax (quad-local rows) ----
            float mx0 = NEGINF, mx1 = NEGINF;
            #pragma unroll
            for (int nt = 0; nt < 8; ++nt) {
                mx0 = fmaxf(mx0, fmaxf(sc[nt][0], sc[nt][1]));
                mx1 = fmaxf(mx1, fmaxf(sc[nt][2], sc[nt][3]));
            }
            mx0 = fmaxf(mx0, __shfl_xor_sync(0xffffffffu, mx0, 1));
            mx0 = fmaxf(mx0, __shfl_xor_sync(0xffffffffu, mx0, 2));
            mx1 = fmaxf(mx1, __shfl_xor_sync(0xffffffffu, mx1, 1));
            mx1 = fmaxf(mx1, __shfl_xor_sync(0xffffffffu, mx1, 2));

            float mn0 = fmaxf(m0r, mx0), mn1 = fmaxf(m1r, mx1);
            float mue0 = (mn0 == NEGINF) ? 0.f : mn0;
            float mue1 = (mn1 == NEGINF) ? 0.f : mn1;
            float al0 = __expf(m0r - mue0), al1 = __expf(m1r - mue1);

            float sum0 = 0.f, sum1 = 0.f;
            #pragma unroll
            for (int nt = 0; nt < 8; ++nt) {
                float p0 = __expf(sc[nt][0] - mue0);
                float p1 = __expf(sc[nt][1] - mue0);
                float p2 = __expf(sc[nt][2] - mue1);
                float p3 = __expf(sc[nt][3] - mue1);
                sum0 += p0 + p1;  sum1 += p2 + p3;
                split2(p0, p1, ph2[nt*2],   pl2[nt*2]);
                split2(p2, p3, ph2[nt*2+1], pl2[nt*2+1]);
            }
            sum0 += __shfl_xor_sync(0xffffffffu, sum0, 1);
            sum0 += __shfl_xor_sync(0xffffffffu, sum0, 2);
            sum1 += __shfl_xor_sync(0xffffffffu, sum1, 1);
            sum1 += __shfl_xor_sync(0xffffffffu, sum1, 2);

            l0 = l0*al0 + sum0;  l1 = l1*al1 + sum1;
            m0r = mn0;  m1r = mn1;

            // rescale O only if some row's max grew (skip common case)
            bool need = (al0 < 1.f) || (al1 < 1.f);
            if (__ballot_sync(0xffffffffu, need)) {
                #pragma unroll
                for (int nt = 0; nt < 16; ++nt) {
                    o[nt][0] *= al0;  o[nt][1] *= al0;
                    o[nt][2] *= al1;  o[nt][3] *= al1;
                }
            }

            // ---- O += P V ----
            const u32 vb = sb + VST + (u32)(j & 1)*VSTG;
            #pragma unroll
            for (int t = 0; t < 4; ++t) {
                #pragma unroll
                for (int nbp = 0; nbp < 8; ++nbp) {
                    u32 vh[4], vl[4];
                    u32 ba = vb + (u32)((nbp*16 + bRow)*VSB + (t*16 + bKB)*2);
                    ldsm4(ba,       vh[0], vh[1], vh[2], vh[3]);
                    ldsm4(ba + VVL, vl[0], vl[1], vl[2], vl[3]);
                    mma16816(o[nbp*2],   ph2[4*t],ph2[4*t+1],ph2[4*t+2],ph2[4*t+3], vh[0], vh[1]);
                    mma16816(o[nbp*2],   ph2[4*t],ph2[4*t+1],ph2[4*t+2],ph2[4*t+3], vl[0], vl[1]);
                    mma16816(o[nbp*2],   pl2[4*t],pl2[4*t+1],pl2[4*t+2],pl2[4*t+3], vh[0], vh[1]);
                    mma16816(o[nbp*2+1], ph2[4*t],ph2[4*t+1],ph2[4*t+2],ph2[4*t+3], vh[2], vh[3]);
                    mma16816(o[nbp*2+1], ph2[4*t],ph2[4*t+1],ph2[4*t+2],ph2[4*t+3], vl[2], vl[3]);
                    mma16816(o[nbp*2+1], pl2[4*t],pl2[4*t+1],pl2[4*t+2],pl2[4*t+3], vh[2], vh[3]);
                }
            }
        };

        #pragma unroll 1
        for (int j = j0; j < j1; j += 2) {
            step(j, sA, sB);
            if (j + 1 < j1) step(j + 1, sB, sA);
        }

        // ---- store partials ----
        const int gr0 = brow + rl0, gr1 = brow + rl1;
        #pragma unroll
        for (int nt = 0; nt < 16; ++nt) {
            const int col = nt*8 + (lane & 3)*2;
            *(float2*)&g_Op[(size_t)gr0*DH + col] = make_float2(o[nt][0], o[nt][1]);
            *(float2*)&g_Op[(size_t)gr1*DH + col] = make_float2(o[nt][2], o[nt][3]);
        }
        if ((lane & 3) == 0) {
            g_mrow[gr0] = m0r;  g_lrow[gr0] = l0;
            g_mrow[gr1] = m1r;  g_lrow[gr1] = l1;
        }
    }
}

// =====================================================================
// Kernel 3: merge 4 KV-quarter partials per row (LSE combine).
// =====================================================================
__global__ void merge_kernel(float* __restrict__ Out)
{
    const int row = blockIdx.x;
    const int d = threadIdx.x;
    float mv[4], lv[4];
    float mmax = NEGINF;
    #pragma unroll
    for (int q = 0; q < 4; ++q) {
        mv[q] = g_mrow[q*SEQ + row];
        lv[q] = g_lrow[q*SEQ + row];
        if (lv[q] > 0.f) mmax = fmaxf(mmax, mv[q]);
    }
    float acc = 0.f, ws = 0.f;
    #pragma unroll
    for (int q = 0; q < 4; ++q) {
        if (lv[q] > 0.f) {
            float wgt = __expf(mv[q] - mmax);
            acc += wgt * g_Op[((size_t)q*SEQ + row)*DH + d];
            ws  += wgt * lv[q];
        }
    }
    Out[(size_t)row*DH + d] = acc / ws;
}

// =====================================================================
extern "C" void kernel_launch(void* const* d_in, const int* in_sizes, int n_in,
                              void* d_out, int out_size)
{
    (void)in_sizes; (void)n_in; (void)out_size;
    const float* X  = (const float*)d_in[0];
    const float* Wq = (const float*)d_in[1];
    const float* Wk = (const float*)d_in[2];
    const float* Wv = (const float*)d_in[3];

    const int nTot = SEQ*DM/4 + 3*DH*DM/4;
    split_all_kernel<<<(nTot + 255)/256, 256>>>(
        (const float4*)X, (const float4*)Wq, (const float4*)Wk, (const float4*)Wv);

    const int PSM = 2*PSSZ;                 // 110592
    const int ASM = VST + 2*VSTG;           // 212992
    cudaFuncSetAttribute(proj_kernel, cudaFuncAttributeMaxDynamicSharedMemorySize, PSM);
    cudaFuncSetAttribute(attn_kernel, cudaFuncAttributeMaxDynamicSharedMemorySize, ASM);

    proj_kernel<<<dim3(128, 3), 256, PSM>>>();
    attn_kernel<<<128, 256, ASM>>>();
    merge_kernel<<<SEQ, 128>>>((float*)d_out);
}